// round 1
// baseline (speedup 1.0000x reference)
#include <cuda_runtime.h>
#include <cuda_bf16.h>
#include <cstdint>

#define T_LEN 4096
#define E_DIM 256
#define H_DIM 512
#define G4    2048
#define TAGS  50
#define NCTA_DIR 64
#define NCTA 128

// ---------------- device scratch (no allocations allowed) ----------------
__device__ float g_Gx[2][(size_t)T_LEN * G4];   // x-projection + biases, per dir (67 MB)
__device__ float g_hs[2][(size_t)T_LEN * H_DIM]; // hidden states per dir (16.8 MB)
__device__ unsigned g_cnt;
__device__ unsigned g_gen;

// ---------------- Kernel 1: Gx[dir][t][row] = emb[sent[t]] @ W_ih^T + b_ih + b_hh --------
// Classic fp32 SMEM-tiled GEMM, M=4096 (t), N=2048 (gate rows), K=256.
#define BM 64
#define BN 64
#define BK 16

__global__ __launch_bounds__(256) void xproj_kernel(
    const int* __restrict__ sent, const float* __restrict__ emb,
    const float* __restrict__ Wih_f, const float* __restrict__ bih_f, const float* __restrict__ bhh_f,
    const float* __restrict__ Wih_b, const float* __restrict__ bih_b, const float* __restrict__ bhh_b)
{
    const int dir = blockIdx.z;
    const float* __restrict__ Wih = dir ? Wih_b : Wih_f;
    const float* __restrict__ bih = dir ? bih_b : bih_f;
    const float* __restrict__ bhh = dir ? bhh_b : bhh_f;
    float* __restrict__ C = g_Gx[dir];

    // reset grid-barrier state once per launch (stream-ordered before recurrence)
    if (blockIdx.x == 0 && blockIdx.y == 0 && dir == 0 && threadIdx.x == 0) {
        g_cnt = 0u;
        g_gen = 0u;
    }

    __shared__ float As[BK][BM + 4];
    __shared__ float Bs[BK][BN + 4];
    __shared__ int   sidx[BM];

    const int tid = threadIdx.x;
    const int tx = tid & 15;       // 16 cols of 4
    const int ty = tid >> 4;       // 16 rows of 4
    const int t0 = blockIdx.y * BM;
    const int n0 = blockIdx.x * BN;

    if (tid < BM) sidx[tid] = sent[t0 + tid];
    __syncthreads();

    float acc[4][4];
#pragma unroll
    for (int i = 0; i < 4; i++)
#pragma unroll
        for (int j = 0; j < 4; j++) acc[i][j] = 0.f;

    const int li = tid >> 2;        // 0..63
    const int lk = (tid & 3) * 4;   // 0,4,8,12

    for (int k0 = 0; k0 < E_DIM; k0 += BK) {
        const float4 av = *(const float4*)&emb[(size_t)sidx[li] * E_DIM + k0 + lk];
        const float4 bv = *(const float4*)&Wih[(size_t)(n0 + li) * E_DIM + k0 + lk];
        __syncthreads();
        As[lk + 0][li] = av.x; As[lk + 1][li] = av.y; As[lk + 2][li] = av.z; As[lk + 3][li] = av.w;
        Bs[lk + 0][li] = bv.x; Bs[lk + 1][li] = bv.y; Bs[lk + 2][li] = bv.z; Bs[lk + 3][li] = bv.w;
        __syncthreads();
#pragma unroll
        for (int kk = 0; kk < BK; kk++) {
            const float4 a = *(const float4*)&As[kk][ty * 4];
            const float4 b = *(const float4*)&Bs[kk][tx * 4];
            acc[0][0] = fmaf(a.x, b.x, acc[0][0]); acc[0][1] = fmaf(a.x, b.y, acc[0][1]);
            acc[0][2] = fmaf(a.x, b.z, acc[0][2]); acc[0][3] = fmaf(a.x, b.w, acc[0][3]);
            acc[1][0] = fmaf(a.y, b.x, acc[1][0]); acc[1][1] = fmaf(a.y, b.y, acc[1][1]);
            acc[1][2] = fmaf(a.y, b.z, acc[1][2]); acc[1][3] = fmaf(a.y, b.w, acc[1][3]);
            acc[2][0] = fmaf(a.z, b.x, acc[2][0]); acc[2][1] = fmaf(a.z, b.y, acc[2][1]);
            acc[2][2] = fmaf(a.z, b.z, acc[2][2]); acc[2][3] = fmaf(a.z, b.w, acc[2][3]);
            acc[3][0] = fmaf(a.w, b.x, acc[3][0]); acc[3][1] = fmaf(a.w, b.y, acc[3][1]);
            acc[3][2] = fmaf(a.w, b.z, acc[3][2]); acc[3][3] = fmaf(a.w, b.w, acc[3][3]);
        }
    }

    const int n = n0 + tx * 4;
    float4 bias;
    bias.x = bih[n + 0] + bhh[n + 0];
    bias.y = bih[n + 1] + bhh[n + 1];
    bias.z = bih[n + 2] + bhh[n + 2];
    bias.w = bih[n + 3] + bhh[n + 3];
#pragma unroll
    for (int i = 0; i < 4; i++) {
        const int t = t0 + ty * 4 + i;
        float4 r;
        r.x = acc[i][0] + bias.x;
        r.y = acc[i][1] + bias.y;
        r.z = acc[i][2] + bias.z;
        r.w = acc[i][3] + bias.w;
        *(float4*)&C[(size_t)t * G4 + n] = r;
    }
}

// ---------------- Kernel 2: persistent bidirectional LSTM recurrence ----------------
// 128 CTAs: CTA b -> dir = b/64, hidden-unit slice of 8 units (32 W_hh rows).
// Each warp owns 4 rows; W_hh rows live in registers (16 floats/lane/row).
// Per step: stage h_prev (512 f32) into SMEM, 64 FFMA/thread matvec, warp butterfly
// reduce, gate nonlinearity on 8 lanes, store h slice, software grid barrier.

__device__ __forceinline__ float sigmf(float x) { return 1.f / (1.f + __expf(-x)); }
__device__ __forceinline__ float tanhf_fast(float x) {
    const float e = __expf(-2.f * x);
    return (1.f - e) / (1.f + e);
}

__global__ __launch_bounds__(256, 1) void lstm_rec_kernel(
    const float* __restrict__ Whhf, const float* __restrict__ Whhb)
{
    const int tid  = threadIdx.x;
    const int lane = tid & 31;
    const int w    = tid >> 5;
    const int bid  = blockIdx.x;
    const int dir  = bid >> 6;       // 0 = forward, 1 = backward
    const int s    = bid & 63;
    const int u0   = s << 3;         // first of 8 hidden units owned by this CTA

    const float* __restrict__ Whh = dir ? Whhb : Whhf;
    const float* __restrict__ Gx  = g_Gx[dir];
    float* __restrict__ hs        = g_hs[dir];

    __shared__ float h_s[H_DIM];
    __shared__ float gates_s[32];
    __shared__ float c_s[8];
    if (tid < 8) c_s[tid] = 0.f;

    // rows: idx = w*4 + r in [0,32); gate q = idx>>3; unit j = idx&7; row = q*512 + u0 + j
    const int idx0 = w * 4;
    int rows[4];
#pragma unroll
    for (int r = 0; r < 4; r++) {
        const int idx = idx0 + r;
        rows[r] = (idx >> 3) * H_DIM + u0 + (idx & 7);
    }
    float wr0[16], wr1[16], wr2[16], wr3[16];
#pragma unroll
    for (int jj = 0; jj < 16; jj++) {
        wr0[jj] = __ldg(&Whh[(size_t)rows[0] * H_DIM + lane + 32 * jj]);
        wr1[jj] = __ldg(&Whh[(size_t)rows[1] * H_DIM + lane + 32 * jj]);
        wr2[jj] = __ldg(&Whh[(size_t)rows[2] * H_DIM + lane + 32 * jj]);
        wr3[jj] = __ldg(&Whh[(size_t)rows[3] * H_DIM + lane + 32 * jj]);
    }

    for (int step = 0; step < T_LEN; step++) {
        const int t = dir ? (T_LEN - 1 - step) : step;

        // stage h_{t-1} (or zeros at step 0) into SMEM; L1-bypass reads (cross-CTA data)
        if (step == 0) {
            ((float2*)h_s)[tid] = make_float2(0.f, 0.f);
        } else {
            const int tp = dir ? (t + 1) : (t - 1);
            ((float2*)h_s)[tid] = __ldcg(((const float2*)&hs[(size_t)tp * H_DIM]) + tid);
        }
        __syncthreads();

        float a0 = 0.f, a1 = 0.f, a2 = 0.f, a3 = 0.f;
#pragma unroll
        for (int jj = 0; jj < 16; jj++) {
            const float hv = h_s[lane + (jj << 5)];
            a0 = fmaf(wr0[jj], hv, a0);
            a1 = fmaf(wr1[jj], hv, a1);
            a2 = fmaf(wr2[jj], hv, a2);
            a3 = fmaf(wr3[jj], hv, a3);
        }
#pragma unroll
        for (int m = 16; m > 0; m >>= 1) {
            a0 += __shfl_xor_sync(0xffffffffu, a0, m);
            a1 += __shfl_xor_sync(0xffffffffu, a1, m);
            a2 += __shfl_xor_sync(0xffffffffu, a2, m);
            a3 += __shfl_xor_sync(0xffffffffu, a3, m);
        }
        if (lane < 4) {
            const float v = (lane == 0) ? a0 : (lane == 1) ? a1 : (lane == 2) ? a2 : a3;
            const int idx = idx0 + lane;
            const int row = (idx >> 3) * H_DIM + u0 + (idx & 7);
            gates_s[idx] = v + __ldg(&Gx[(size_t)t * G4 + row]);
        }
        __syncthreads();

        if (tid < 8) {
            const int j  = tid;
            const float iv = sigmf(gates_s[j]);
            const float fv = sigmf(gates_s[8 + j]);
            const float gv = tanhf_fast(gates_s[16 + j]);
            const float ov = sigmf(gates_s[24 + j]);
            const float c  = fmaf(fv, c_s[j], iv * gv);
            c_s[j] = c;
            hs[(size_t)t * H_DIM + u0 + j] = ov * tanhf_fast(c);
        }
        __syncthreads();

        // software grid barrier (monotonic counter; no reset races)
        if (tid == 0) {
            __threadfence();
            const unsigned target = (unsigned)NCTA * (unsigned)(step + 1);
            const unsigned old = atomicAdd(&g_cnt, 1u);
            if (old == target - 1u) {
                atomicExch(&g_gen, (unsigned)(step + 1));
            } else {
                while (*((volatile unsigned*)&g_gen) < (unsigned)(step + 1)) { }
            }
            __threadfence();
        }
        __syncthreads();
    }
}

// ---------------- Kernel 3: out[t][tag] = concat(hs_f[t], hs_b[t]) @ W_out^T + b_out ----
__global__ __launch_bounds__(256) void outproj_kernel(
    const float* __restrict__ Wout, const float* __restrict__ bout, float* __restrict__ out)
{
    __shared__ float xs[4][2 * H_DIM];
    const int tid = threadIdx.x;
    const int t0 = blockIdx.x * 4;

    for (int i = tid; i < 4 * 2 * H_DIM; i += 256) {
        const int tt = i >> 10;
        const int k  = i & 1023;
        const int t  = t0 + tt;
        xs[tt][k] = (k < H_DIM) ? __ldg(&g_hs[0][(size_t)t * H_DIM + k])
                                : __ldg(&g_hs[1][(size_t)t * H_DIM + (k - H_DIM)]);
    }
    __syncthreads();

    const int tag = tid & 63;
    const int tt  = tid >> 6;
    if (tag < TAGS) {
        float acc = __ldg(&bout[tag]);
        const float4* __restrict__ wrow = (const float4*)&Wout[(size_t)tag * (2 * H_DIM)];
        const float4* __restrict__ xv   = (const float4*)xs[tt];
#pragma unroll 8
        for (int k4 = 0; k4 < (2 * H_DIM) / 4; k4++) {
            const float4 wv = __ldg(&wrow[k4]);
            const float4 x  = xv[k4];
            acc = fmaf(wv.x, x.x, acc);
            acc = fmaf(wv.y, x.y, acc);
            acc = fmaf(wv.z, x.z, acc);
            acc = fmaf(wv.w, x.w, acc);
        }
        out[(size_t)(t0 + tt) * TAGS + tag] = acc;
    }
}

// ---------------- launch ----------------
extern "C" void kernel_launch(void* const* d_in, const int* in_sizes, int n_in,
                              void* d_out, int out_size)
{
    const int*   sent  = (const int*)d_in[0];
    const float* emb   = (const float*)d_in[1];
    const float* Wih_f = (const float*)d_in[2];
    const float* Whh_f = (const float*)d_in[3];
    const float* bih_f = (const float*)d_in[4];
    const float* bhh_f = (const float*)d_in[5];
    const float* Wih_b = (const float*)d_in[6];
    const float* Whh_b = (const float*)d_in[7];
    const float* bih_b = (const float*)d_in[8];
    const float* bhh_b = (const float*)d_in[9];
    const float* Wout  = (const float*)d_in[10];
    const float* bout  = (const float*)d_in[11];
    float* out = (float*)d_out;

    dim3 gx(G4 / BN, T_LEN / BM, 2);
    xproj_kernel<<<gx, 256>>>(sent, emb, Wih_f, bih_f, bhh_f, Wih_b, bih_b, bhh_b);
    lstm_rec_kernel<<<NCTA, 256>>>(Whh_f, Whh_b);
    outproj_kernel<<<T_LEN / 4, 256>>>(Wout, bout, out);
}

// round 4
// speedup vs baseline: 1.3654x; 1.3654x over previous
#include <cuda_runtime.h>
#include <cuda_bf16.h>
#include <cstdint>

#define T_LEN 4096
#define E_DIM 256
#define H_DIM 512
#define G4    2048
#define TAGS  50
#define NCTA  128

// ---------------- device scratch (no allocations allowed) ----------------
__device__ float g_Gx[2][(size_t)T_LEN * G4];     // x-projection + biases, per dir
__device__ float g_hs[2][(size_t)T_LEN * H_DIM];  // hidden states per dir
__device__ unsigned g_flag[2][64];                // per-CTA progress flags (reset each launch)

// ---------------- Kernel 1: Gx[dir][t][row] = emb[sent[t]] @ W_ih^T + b_ih + b_hh --------
#define BM 64
#define BN 64
#define BK 16

__global__ __launch_bounds__(256) void xproj_kernel(
    const int* __restrict__ sent, const float* __restrict__ emb,
    const float* __restrict__ Wih_f, const float* __restrict__ bih_f, const float* __restrict__ bhh_f,
    const float* __restrict__ Wih_b, const float* __restrict__ bih_b, const float* __restrict__ bhh_b)
{
    const int dir = blockIdx.z;
    const float* __restrict__ Wih = dir ? Wih_b : Wih_f;
    const float* __restrict__ bih = dir ? bih_b : bih_f;
    const float* __restrict__ bhh = dir ? bhh_b : bhh_f;
    float* __restrict__ C = g_Gx[dir];

    // reset progress flags once per launch (stream-ordered before the recurrence kernel)
    if (blockIdx.x == 0 && blockIdx.y == 0 && dir == 0 && threadIdx.x < 128) {
        g_flag[threadIdx.x >> 6][threadIdx.x & 63] = 0u;
    }

    __shared__ float As[BK][BM + 4];
    __shared__ float Bs[BK][BN + 4];
    __shared__ int   sidx[BM];

    const int tid = threadIdx.x;
    const int tx = tid & 15;
    const int ty = tid >> 4;
    const int t0 = blockIdx.y * BM;
    const int n0 = blockIdx.x * BN;

    if (tid < BM) sidx[tid] = sent[t0 + tid];
    __syncthreads();

    float acc[4][4];
#pragma unroll
    for (int i = 0; i < 4; i++)
#pragma unroll
        for (int j = 0; j < 4; j++) acc[i][j] = 0.f;

    const int li = tid >> 2;
    const int lk = (tid & 3) * 4;

    for (int k0 = 0; k0 < E_DIM; k0 += BK) {
        const float4 av = *(const float4*)&emb[(size_t)sidx[li] * E_DIM + k0 + lk];
        const float4 bv = *(const float4*)&Wih[(size_t)(n0 + li) * E_DIM + k0 + lk];
        __syncthreads();
        As[lk + 0][li] = av.x; As[lk + 1][li] = av.y; As[lk + 2][li] = av.z; As[lk + 3][li] = av.w;
        Bs[lk + 0][li] = bv.x; Bs[lk + 1][li] = bv.y; Bs[lk + 2][li] = bv.z; Bs[lk + 3][li] = bv.w;
        __syncthreads();
#pragma unroll
        for (int kk = 0; kk < BK; kk++) {
            const float4 a = *(const float4*)&As[kk][ty * 4];
            const float4 b = *(const float4*)&Bs[kk][tx * 4];
            acc[0][0] = fmaf(a.x, b.x, acc[0][0]); acc[0][1] = fmaf(a.x, b.y, acc[0][1]);
            acc[0][2] = fmaf(a.x, b.z, acc[0][2]); acc[0][3] = fmaf(a.x, b.w, acc[0][3]);
            acc[1][0] = fmaf(a.y, b.x, acc[1][0]); acc[1][1] = fmaf(a.y, b.y, acc[1][1]);
            acc[1][2] = fmaf(a.y, b.z, acc[1][2]); acc[1][3] = fmaf(a.y, b.w, acc[1][3]);
            acc[2][0] = fmaf(a.z, b.x, acc[2][0]); acc[2][1] = fmaf(a.z, b.y, acc[2][1]);
            acc[2][2] = fmaf(a.z, b.z, acc[2][2]); acc[2][3] = fmaf(a.z, b.w, acc[2][3]);
            acc[3][0] = fmaf(a.w, b.x, acc[3][0]); acc[3][1] = fmaf(a.w, b.y, acc[3][1]);
            acc[3][2] = fmaf(a.w, b.z, acc[3][2]); acc[3][3] = fmaf(a.w, b.w, acc[3][3]);
        }
    }

    const int n = n0 + tx * 4;
    float4 bias;
    bias.x = bih[n + 0] + bhh[n + 0];
    bias.y = bih[n + 1] + bhh[n + 1];
    bias.z = bih[n + 2] + bhh[n + 2];
    bias.w = bih[n + 3] + bhh[n + 3];
#pragma unroll
    for (int i = 0; i < 4; i++) {
        const int t = t0 + ty * 4 + i;
        float4 r;
        r.x = acc[i][0] + bias.x;
        r.y = acc[i][1] + bias.y;
        r.z = acc[i][2] + bias.z;
        r.w = acc[i][3] + bias.w;
        *(float4*)&C[(size_t)t * G4 + n] = r;
    }
}

// ---------------- Kernel 2: persistent recurrence, distributed-flag sync ----------------
// Proven round-1 memory primitives (plain h stores, threadfence + atomicExch release,
// volatile poll + threadfence acquire), distributed per-CTA flags for parallel release.
__device__ __forceinline__ float sigmf(float x) { return 1.f / (1.f + __expf(-x)); }
__device__ __forceinline__ float tanhf_fast(float x) {
    const float e = __expf(-2.f * x);
    return (1.f - e) / (1.f + e);
}

__global__ __launch_bounds__(256, 1) void lstm_rec_kernel(
    const float* __restrict__ Whhf, const float* __restrict__ Whhb)
{
    const int tid  = threadIdx.x;
    const int lane = tid & 31;
    const int w    = tid >> 5;
    const int bid  = blockIdx.x;
    const int dir  = bid >> 6;       // 0 = forward, 1 = backward
    const int s    = bid & 63;
    const int u0   = s << 3;         // first of 8 hidden units owned by this CTA

    const float* __restrict__ Whh = dir ? Whhb : Whhf;
    const float* __restrict__ Gx  = g_Gx[dir];
    float* __restrict__ hs        = g_hs[dir];

    __shared__ float h_s[H_DIM];
    __shared__ float gates_s[32];
    __shared__ float c_s[8];
    if (tid < 8) c_s[tid] = 0.f;

    // warp w owns rows idx = w*4 + r, r in [0,4); gate q = idx>>3; unit j = idx&7
    const int idx0 = w * 4;
    int rows[4];
#pragma unroll
    for (int r = 0; r < 4; r++) {
        const int idx = idx0 + r;
        rows[r] = (idx >> 3) * H_DIM + u0 + (idx & 7);
    }
    float wr0[16], wr1[16], wr2[16], wr3[16];
#pragma unroll
    for (int jj = 0; jj < 16; jj++) {
        wr0[jj] = __ldg(&Whh[(size_t)rows[0] * H_DIM + lane + 32 * jj]);
        wr1[jj] = __ldg(&Whh[(size_t)rows[1] * H_DIM + lane + 32 * jj]);
        wr2[jj] = __ldg(&Whh[(size_t)rows[2] * H_DIM + lane + 32 * jj]);
        wr3[jj] = __ldg(&Whh[(size_t)rows[3] * H_DIM + lane + 32 * jj]);
    }
    const int myrow = (lane < 4) ? rows[lane] : rows[0];

    __syncthreads();

    for (int step = 0; step < T_LEN; step++) {
        const int t = dir ? (T_LEN - 1 - step) : step;

        // prefetch this step's Gx contribution (independent of h) to overlap the wait
        float gx = 0.f;
        if (lane < 4) gx = __ldg(&Gx[(size_t)t * G4 + myrow]);

        // acquire h_{t-1}
        if (step == 0) {
            ((float2*)h_s)[tid] = make_float2(0.f, 0.f);
            __syncthreads();
        } else {
            const int tp = dir ? (t + 1) : (t - 1);
            // wait for all same-direction producer CTAs to finish step-1
            if (tid < 64) {
                const unsigned want = (unsigned)step;
                while (*((volatile unsigned*)&g_flag[dir][tid]) < want) { }
            }
            __threadfence();
            __syncthreads();   // all threads see: every producer published h[tp]
            ((float2*)h_s)[tid] = __ldcg(((const float2*)&hs[(size_t)tp * H_DIM]) + tid);
            __syncthreads();
        }

        float a0 = 0.f, a1 = 0.f, a2 = 0.f, a3 = 0.f;
#pragma unroll
        for (int jj = 0; jj < 16; jj++) {
            const float hv = h_s[lane + (jj << 5)];
            a0 = fmaf(wr0[jj], hv, a0);
            a1 = fmaf(wr1[jj], hv, a1);
            a2 = fmaf(wr2[jj], hv, a2);
            a3 = fmaf(wr3[jj], hv, a3);
        }
#pragma unroll
        for (int m = 16; m > 0; m >>= 1) {
            a0 += __shfl_xor_sync(0xffffffffu, a0, m);
            a1 += __shfl_xor_sync(0xffffffffu, a1, m);
            a2 += __shfl_xor_sync(0xffffffffu, a2, m);
            a3 += __shfl_xor_sync(0xffffffffu, a3, m);
        }
        if (lane < 4) {
            const float v = (lane == 0) ? a0 : (lane == 1) ? a1 : (lane == 2) ? a2 : a3;
            gates_s[idx0 + lane] = v + gx;
        }
        __syncthreads();

        if (tid < 8) {
            const int j  = tid;
            const float iv = sigmf(gates_s[j]);
            const float fv = sigmf(gates_s[8 + j]);
            const float gv = tanhf_fast(gates_s[16 + j]);
            const float ov = sigmf(gates_s[24 + j]);
            const float c  = fmaf(fv, c_s[j], iv * gv);
            c_s[j] = c;
            hs[(size_t)t * H_DIM + u0 + j] = ov * tanhf_fast(c);   // plain store (round-1 proven)
        }
        __syncthreads();

        // publish progress with a STRONG release (round-1 proven primitive),
        // distributed over 64 distinct addresses -> no serialization
        if (tid == 0) {
            __threadfence();
            atomicExch(&g_flag[dir][s], (unsigned)(step + 1));
        }
    }
}

// ---------------- Kernel 3: out[t][tag] = concat(hs_f[t], hs_b[t]) @ W_out^T + b_out ----
__global__ __launch_bounds__(256) void outproj_kernel(
    const float* __restrict__ Wout, const float* __restrict__ bout, float* __restrict__ out)
{
    __shared__ float xs[4][2 * H_DIM];
    const int tid = threadIdx.x;
    const int t0 = blockIdx.x * 4;

    for (int i = tid; i < 4 * 2 * H_DIM; i += 256) {
        const int tt = i >> 10;
        const int k  = i & 1023;
        const int t  = t0 + tt;
        xs[tt][k] = (k < H_DIM) ? __ldg(&g_hs[0][(size_t)t * H_DIM + k])
                                : __ldg(&g_hs[1][(size_t)t * H_DIM + (k - H_DIM)]);
    }
    __syncthreads();

    const int tag = tid & 63;
    const int tt  = tid >> 6;
    if (tag < TAGS) {
        float acc = __ldg(&bout[tag]);
        const float4* __restrict__ wrow = (const float4*)&Wout[(size_t)tag * (2 * H_DIM)];
        const float4* __restrict__ xv   = (const float4*)xs[tt];
#pragma unroll 8
        for (int k4 = 0; k4 < (2 * H_DIM) / 4; k4++) {
            const float4 wv = __ldg(&wrow[k4]);
            const float4 x  = xv[k4];
            acc = fmaf(wv.x, x.x, acc);
            acc = fmaf(wv.y, x.y, acc);
            acc = fmaf(wv.z, x.z, acc);
            acc = fmaf(wv.w, x.w, acc);
        }
        out[(size_t)(t0 + tt) * TAGS + tag] = acc;
    }
}

// ---------------- launch ----------------
extern "C" void kernel_launch(void* const* d_in, const int* in_sizes, int n_in,
                              void* d_out, int out_size)
{
    const int*   sent  = (const int*)d_in[0];
    const float* emb   = (const float*)d_in[1];
    const float* Wih_f = (const float*)d_in[2];
    const float* Whh_f = (const float*)d_in[3];
    const float* bih_f = (const float*)d_in[4];
    const float* bhh_f = (const float*)d_in[5];
    const float* Wih_b = (const float*)d_in[6];
    const float* Whh_b = (const float*)d_in[7];
    const float* bih_b = (const float*)d_in[8];
    const float* bhh_b = (const float*)d_in[9];
    const float* Wout  = (const float*)d_in[10];
    const float* bout  = (const float*)d_in[11];
    float* out = (float*)d_out;

    dim3 gx(G4 / BN, T_LEN / BM, 2);
    xproj_kernel<<<gx, 256>>>(sent, emb, Wih_f, bih_f, bhh_f, Wih_b, bih_b, bhh_b);
    lstm_rec_kernel<<<NCTA, 256>>>(Whh_f, Whh_b);
    outproj_kernel<<<T_LEN / 4, 256>>>(Wout, bout, out);
}

// round 5
// speedup vs baseline: 1.9942x; 1.4606x over previous
#include <cuda_runtime.h>
#include <cuda_bf16.h>
#include <cstdint>

#define T_LEN 4096
#define E_DIM 256
#define H_DIM 512
#define G4    2048
#define TAGS  50
#define NCTA  128

// ---------------- device scratch (no allocations allowed) ----------------
__device__ float g_Gx[2][(size_t)T_LEN * G4];                  // x-projection + biases
__device__ unsigned long long g_hp[2][T_LEN][H_DIM];           // packets {tag:32 | h:32}
__device__ unsigned g_epoch;                                   // bumped once per launch

// ---------------- Kernel 1: Gx[dir][t][row] = emb[sent[t]] @ W_ih^T + b_ih + b_hh --------
#define BM 64
#define BN 64
#define BK 16

__global__ __launch_bounds__(256) void xproj_kernel(
    const int* __restrict__ sent, const float* __restrict__ emb,
    const float* __restrict__ Wih_f, const float* __restrict__ bih_f, const float* __restrict__ bhh_f,
    const float* __restrict__ Wih_b, const float* __restrict__ bih_b, const float* __restrict__ bhh_b)
{
    const int dir = blockIdx.z;
    const float* __restrict__ Wih = dir ? Wih_b : Wih_f;
    const float* __restrict__ bih = dir ? bih_b : bih_f;
    const float* __restrict__ bhh = dir ? bhh_b : bhh_f;
    float* __restrict__ C = g_Gx[dir];

    // bump epoch once per launch (stream-ordered before the recurrence kernel)
    if (blockIdx.x == 0 && blockIdx.y == 0 && dir == 0 && threadIdx.x == 0) {
        g_epoch = g_epoch + 1u;
    }

    __shared__ float As[BK][BM + 4];
    __shared__ float Bs[BK][BN + 4];
    __shared__ int   sidx[BM];

    const int tid = threadIdx.x;
    const int tx = tid & 15;
    const int ty = tid >> 4;
    const int t0 = blockIdx.y * BM;
    const int n0 = blockIdx.x * BN;

    if (tid < BM) sidx[tid] = sent[t0 + tid];
    __syncthreads();

    float acc[4][4];
#pragma unroll
    for (int i = 0; i < 4; i++)
#pragma unroll
        for (int j = 0; j < 4; j++) acc[i][j] = 0.f;

    const int li = tid >> 2;
    const int lk = (tid & 3) * 4;

    for (int k0 = 0; k0 < E_DIM; k0 += BK) {
        const float4 av = *(const float4*)&emb[(size_t)sidx[li] * E_DIM + k0 + lk];
        const float4 bv = *(const float4*)&Wih[(size_t)(n0 + li) * E_DIM + k0 + lk];
        __syncthreads();
        As[lk + 0][li] = av.x; As[lk + 1][li] = av.y; As[lk + 2][li] = av.z; As[lk + 3][li] = av.w;
        Bs[lk + 0][li] = bv.x; Bs[lk + 1][li] = bv.y; Bs[lk + 2][li] = bv.z; Bs[lk + 3][li] = bv.w;
        __syncthreads();
#pragma unroll
        for (int kk = 0; kk < BK; kk++) {
            const float4 a = *(const float4*)&As[kk][ty * 4];
            const float4 b = *(const float4*)&Bs[kk][tx * 4];
            acc[0][0] = fmaf(a.x, b.x, acc[0][0]); acc[0][1] = fmaf(a.x, b.y, acc[0][1]);
            acc[0][2] = fmaf(a.x, b.z, acc[0][2]); acc[0][3] = fmaf(a.x, b.w, acc[0][3]);
            acc[1][0] = fmaf(a.y, b.x, acc[1][0]); acc[1][1] = fmaf(a.y, b.y, acc[1][1]);
            acc[1][2] = fmaf(a.y, b.z, acc[1][2]); acc[1][3] = fmaf(a.y, b.w, acc[1][3]);
            acc[2][0] = fmaf(a.z, b.x, acc[2][0]); acc[2][1] = fmaf(a.z, b.y, acc[2][1]);
            acc[2][2] = fmaf(a.z, b.z, acc[2][2]); acc[2][3] = fmaf(a.z, b.w, acc[2][3]);
            acc[3][0] = fmaf(a.w, b.x, acc[3][0]); acc[3][1] = fmaf(a.w, b.y, acc[3][1]);
            acc[3][2] = fmaf(a.w, b.z, acc[3][2]); acc[3][3] = fmaf(a.w, b.w, acc[3][3]);
        }
    }

    const int n = n0 + tx * 4;
    float4 bias;
    bias.x = bih[n + 0] + bhh[n + 0];
    bias.y = bih[n + 1] + bhh[n + 1];
    bias.z = bih[n + 2] + bhh[n + 2];
    bias.w = bih[n + 3] + bhh[n + 3];
#pragma unroll
    for (int i = 0; i < 4; i++) {
        const int t = t0 + ty * 4 + i;
        float4 r;
        r.x = acc[i][0] + bias.x;
        r.y = acc[i][1] + bias.y;
        r.z = acc[i][2] + bias.z;
        r.w = acc[i][3] + bias.w;
        *(float4*)&C[(size_t)t * G4 + n] = r;
    }
}

// ---------------- Kernel 2: persistent recurrence, single-RT atomic-packet dataflow -----
// sigm(x) = 1/(1+e^-x); tanh(x) = 2*sigm(2x)-1 (single expf chain, no divergence)
__device__ __forceinline__ float sigmf(float x) { return 1.f / (1.f + __expf(-x)); }

__global__ __launch_bounds__(256, 1) void lstm_rec_kernel(
    const float* __restrict__ Whhf, const float* __restrict__ Whhb)
{
    const int tid  = threadIdx.x;
    const int lane = tid & 31;
    const int w    = tid >> 5;
    const int bid  = blockIdx.x;
    const int dir  = bid >> 6;       // 0 = forward, 1 = backward
    const int s    = bid & 63;
    const int u0   = s << 3;         // first of 8 hidden units owned by this CTA

    const float* __restrict__ Whh = dir ? Whhb : Whhf;
    const float* __restrict__ Gx  = g_Gx[dir];

    const unsigned epoch = *((volatile unsigned*)&g_epoch);
    const unsigned tagbase = epoch * 4096u;

    __shared__ float h_s[H_DIM];
    __shared__ float gates_s[32];

    // warp w owns rows idx = w*4 + r; gate q = idx>>3; unit j = idx&7
    const int idx0 = w * 4;
    int rows[4];
#pragma unroll
    for (int r = 0; r < 4; r++) {
        const int idx = idx0 + r;
        rows[r] = (idx >> 3) * H_DIM + u0 + (idx & 7);
    }
    float wr0[16], wr1[16], wr2[16], wr3[16];
#pragma unroll
    for (int jj = 0; jj < 16; jj++) {
        wr0[jj] = __ldg(&Whh[(size_t)rows[0] * H_DIM + lane + 32 * jj]);
        wr1[jj] = __ldg(&Whh[(size_t)rows[1] * H_DIM + lane + 32 * jj]);
        wr2[jj] = __ldg(&Whh[(size_t)rows[2] * H_DIM + lane + 32 * jj]);
        wr3[jj] = __ldg(&Whh[(size_t)rows[3] * H_DIM + lane + 32 * jj]);
    }
    const int myrow = (lane < 4) ? rows[lane] : rows[0];

    float c_reg = 0.f;   // cell state: lane j<8 of warp 0 owns unit u0+j

    // prefetch Gx for step 0
    const int tfirst = dir ? (T_LEN - 1) : 0;
    float gx_cur = (lane < 4) ? __ldg(&Gx[(size_t)tfirst * G4 + myrow]) : 0.f;

    __syncthreads();

    for (int step = 0; step < T_LEN; step++) {
        const int t = dir ? (T_LEN - 1 - step) : step;

        // prefetch next step's Gx (independent) to fully hide DRAM latency
        float gx_next = 0.f;
        if (lane < 4 && step + 1 < T_LEN) {
            const int tn = dir ? (t - 1) : (t + 1);
            gx_next = __ldg(&Gx[(size_t)tn * G4 + myrow]);
        }

        // acquire h_{t-1}: poll 2 atomic 64-bit packets {tag|h}; data rides with the tag
        if (step == 0) {
            ((float2*)h_s)[tid] = make_float2(0.f, 0.f);
        } else {
            const int tp = dir ? (t + 1) : (t - 1);
            const unsigned wtag = tagbase + (unsigned)tp;
            const unsigned long long* p0 = &g_hp[dir][tp][2 * tid + 0];
            const unsigned long long* p1 = &g_hp[dir][tp][2 * tid + 1];
            unsigned long long v0, v1;
            do {
                asm volatile("ld.relaxed.gpu.global.u64 %0, [%1];" : "=l"(v0) : "l"(p0));
            } while ((unsigned)(v0 >> 32) != wtag);
            do {
                asm volatile("ld.relaxed.gpu.global.u64 %0, [%1];" : "=l"(v1) : "l"(p1));
            } while ((unsigned)(v1 >> 32) != wtag);
            h_s[2 * tid + 0] = __uint_as_float((unsigned)v0);
            h_s[2 * tid + 1] = __uint_as_float((unsigned)v1);
        }
        __syncthreads();

        float a0 = 0.f, a1 = 0.f, a2 = 0.f, a3 = 0.f;
#pragma unroll
        for (int jj = 0; jj < 16; jj++) {
            const float hv = h_s[lane + (jj << 5)];
            a0 = fmaf(wr0[jj], hv, a0);
            a1 = fmaf(wr1[jj], hv, a1);
            a2 = fmaf(wr2[jj], hv, a2);
            a3 = fmaf(wr3[jj], hv, a3);
        }
#pragma unroll
        for (int m = 16; m > 0; m >>= 1) {
            a0 += __shfl_xor_sync(0xffffffffu, a0, m);
            a1 += __shfl_xor_sync(0xffffffffu, a1, m);
            a2 += __shfl_xor_sync(0xffffffffu, a2, m);
            a3 += __shfl_xor_sync(0xffffffffu, a3, m);
        }
        if (lane < 4) {
            const float v = (lane == 0) ? a0 : (lane == 1) ? a1 : (lane == 2) ? a2 : a3;
            gates_s[idx0 + lane] = v + gx_cur;
        }
        gx_cur = gx_next;
        __syncthreads();

        // warp 0: one gate per lane (q = lane>>3, unit j = lane&7), shfl-gather, c update
        if (w == 0) {
            const int q = lane >> 3;
            const float x  = gates_s[lane];
            const float xs = (q == 2) ? 2.f * x : x;
            const float sg = sigmf(xs);
            const float nl = (q == 2) ? (2.f * sg - 1.f) : sg;   // tanh for gate g, sigm else

            const int j = lane & 7;
            const float iv = __shfl_sync(0xffffffffu, nl, j);
            const float fv = __shfl_sync(0xffffffffu, nl, 8 + j);
            const float gv = __shfl_sync(0xffffffffu, nl, 16 + j);
            const float ov = __shfl_sync(0xffffffffu, nl, 24 + j);

            if (lane < 8) {
                const float c = fmaf(fv, c_reg, iv * gv);
                c_reg = c;
                const float sc = sigmf(2.f * c);
                const float hval = ov * (2.f * sc - 1.f);        // o * tanh(c)
                const unsigned long long pkt =
                    ((unsigned long long)(tagbase + (unsigned)t) << 32) |
                    (unsigned long long)__float_as_uint(hval);
                unsigned long long* dst = &g_hp[dir][t][u0 + lane];
                asm volatile("st.relaxed.gpu.global.u64 [%0], %1;" :: "l"(dst), "l"(pkt) : "memory");
            }
        }
        __syncthreads();   // protect gates_s / h_s reuse next step
    }
}

// ---------------- Kernel 3: out[t][tag] = concat(hs_f[t], hs_b[t]) @ W_out^T + b_out ----
__global__ __launch_bounds__(256) void outproj_kernel(
    const float* __restrict__ Wout, const float* __restrict__ bout, float* __restrict__ out)
{
    __shared__ float xs[4][2 * H_DIM];
    const int tid = threadIdx.x;
    const int t0 = blockIdx.x * 4;

    for (int i = tid; i < 4 * 2 * H_DIM; i += 256) {
        const int tt = i >> 10;
        const int k  = i & 1023;
        const int t  = t0 + tt;
        const unsigned long long pkt = (k < H_DIM) ? g_hp[0][t][k] : g_hp[1][t][k - H_DIM];
        xs[tt][k] = __uint_as_float((unsigned)pkt);
    }
    __syncthreads();

    const int tag = tid & 63;
    const int tt  = tid >> 6;
    if (tag < TAGS) {
        float acc = __ldg(&bout[tag]);
        const float4* __restrict__ wrow = (const float4*)&Wout[(size_t)tag * (2 * H_DIM)];
        const float4* __restrict__ xv   = (const float4*)xs[tt];
#pragma unroll 8
        for (int k4 = 0; k4 < (2 * H_DIM) / 4; k4++) {
            const float4 wv = __ldg(&wrow[k4]);
            const float4 x  = xv[k4];
            acc = fmaf(wv.x, x.x, acc);
            acc = fmaf(wv.y, x.y, acc);
            acc = fmaf(wv.z, x.z, acc);
            acc = fmaf(wv.w, x.w, acc);
        }
        out[(size_t)(t0 + tt) * TAGS + tag] = acc;
    }
}

// ---------------- launch ----------------
extern "C" void kernel_launch(void* const* d_in, const int* in_sizes, int n_in,
                              void* d_out, int out_size)
{
    const int*   sent  = (const int*)d_in[0];
    const float* emb   = (const float*)d_in[1];
    const float* Wih_f = (const float*)d_in[2];
    const float* Whh_f = (const float*)d_in[3];
    const float* bih_f = (const float*)d_in[4];
    const float* bhh_f = (const float*)d_in[5];
    const float* Wih_b = (const float*)d_in[6];
    const float* Whh_b = (const float*)d_in[7];
    const float* bih_b = (const float*)d_in[8];
    const float* bhh_b = (const float*)d_in[9];
    const float* Wout  = (const float*)d_in[10];
    const float* bout  = (const float*)d_in[11];
    float* out = (float*)d_out;

    dim3 gx(G4 / BN, T_LEN / BM, 2);
    xproj_kernel<<<gx, 256>>>(sent, emb, Wih_f, bih_f, bhh_f, Wih_b, bih_b, bhh_b);
    lstm_rec_kernel<<<NCTA, 256>>>(Whh_f, Whh_b);
    outproj_kernel<<<T_LEN / 4, 256>>>(Wout, bout, out);
}